// round 1
// baseline (speedup 1.0000x reference)
#include <cuda_runtime.h>
#include <math.h>

#define NNODES 20000
#define NEDGES 50000
#define HID 128
#define OUTD 64
#define NPAIRS 128
#define UTOT 256
#define NH 4
#define DH 32
#define DEGCAP 128
#define MCAP (UTOT * DEGCAP)          /* 32768 incident-entry capacity */
#define ACAP (UTOT + MCAP)            /* 33024 active-node capacity */
#define TM 16
#define MAXT_A ((ACAP + TM - 1) / TM) /* 2064 */
#define MAXT_M ((MCAP + TM - 1) / TM) /* 2048 */

// ---------------- device scratch (no allocs allowed) ----------------
__device__ int g_node2slot[NNODES];
__device__ int g_activeNodes[ACAP];
__device__ int g_activeCount;
__device__ int g_totalEntries;
__device__ int g_deg[UTOT];
__device__ int g_incBase[UTOT];
__device__ int g_entryEdge[MCAP];
__device__ int g_entryNbr[MCAP];

__device__ float g_x[ACAP * HID];
__device__ float g_tf[ACAP * HID];
__device__ float g_Ak[ACAP * HID];
__device__ float g_Av[ACAP * HID];
__device__ float g_tfeat[MCAP * HID];
__device__ float g_Bk[MCAP * HID];
__device__ float g_Bv[MCAP * HID];

__device__ __forceinline__ float* selArr(int s) {
    switch (s) {
        case 0: return g_x;
        case 1: return g_tf;
        case 2: return g_Ak;
        case 3: return g_Av;
        case 4: return g_tfeat;
        case 5: return g_Bk;
        default: return g_Bv;
    }
}

__device__ __forceinline__ void ensure_slot(int n) {
    if (g_node2slot[n] == -1) {
        if (atomicCAS(&g_node2slot[n], -1, -2) == -1) {
            int s = atomicAdd(&g_activeCount, 1);
            g_activeNodes[s] = n;
            __threadfence();
            g_node2slot[n] = s;
        }
    }
}

// ---------------- init ----------------
__global__ void k_init() {
    int i = blockIdx.x * blockDim.x + threadIdx.x;
    if (i < NNODES) g_node2slot[i] = -1;
    if (i == 0) { g_activeCount = 0; g_totalEntries = 0; }
}

// ---------------- build incident lists + active slots ----------------
__global__ __launch_bounds__(256) void k_build(const int* __restrict__ ei,
                                               const int* __restrict__ tp) {
    int u = blockIdx.x;
    int tid = threadIdx.x;
    int lane = tid & 31, wid = tid >> 5;
    __shared__ int s_edge[DEGCAP], s_nbr[DEGCAP];
    __shared__ int s_wc[2][8];
    __shared__ int s_base;
    int tgt = tp[u];
    const int* src = ei;
    const int* dst = ei + NEDGES;

    int cnt = 0;  // replicated across all threads (identical value)
    int buf = 0;
    for (int e0 = 0; e0 < NEDGES; e0 += 256) {
        int e = e0 + tid;
        bool match = false;
        int nbr = 0;
        if (e < NEDGES) {
            int s = src[e], d = dst[e];
            if (s == tgt)      { match = true; nbr = d; }
            else if (d == tgt) { match = true; nbr = s; }
        }
        unsigned bal = __ballot_sync(0xffffffffu, match);
        if (lane == 0) s_wc[buf][wid] = __popc(bal);
        __syncthreads();
        int wbase = 0, tot = 0;
#pragma unroll
        for (int w = 0; w < 8; w++) {
            int c = s_wc[buf][w];
            if (w < wid) wbase += c;
            tot += c;
        }
        int pos = cnt + wbase + __popc(bal & ((1u << lane) - 1u));
        if (match && pos < DEGCAP) { s_edge[pos] = e; s_nbr[pos] = nbr; }
        cnt += tot;
        buf ^= 1;
    }
    __syncthreads();

    int c = min(cnt, DEGCAP);
    if (tid == 0) {
        g_deg[u] = c;
        int bse = atomicAdd(&g_totalEntries, c);
        g_incBase[u] = bse;
        s_base = bse;
        ensure_slot(tgt);
    }
    __syncthreads();
    int bse = s_base;
    for (int i = tid; i < c; i += 256) {
        g_entryEdge[bse + i] = s_edge[i];
        int nb = s_nbr[i];
        g_entryNbr[bse + i] = nb;
        ensure_slot(nb);
    }
}

// ---------------- input projection: x = gather(nf) @ in_W.T + in_b ----------------
__global__ __launch_bounds__(128) void k_input(const float* __restrict__ nf,
                                               const float* __restrict__ W,
                                               const float* __restrict__ b) {
    int A = g_activeCount;
    int r0 = blockIdx.x * TM;
    if (r0 >= A) return;
    int tid = threadIdx.x;
    int nrows = min(TM, A - r0);
    __shared__ __align__(16) float Xs[TM][HID];
#pragma unroll
    for (int i = 0; i < TM; i++) {
        float v = 0.f;
        if (i < nrows) {
            int node = g_activeNodes[r0 + i];
            v = nf[node * HID + tid];
        }
        Xs[i][tid] = v;
    }
    __syncthreads();
    float acc[TM];
#pragma unroll
    for (int i = 0; i < TM; i++) acc[i] = 0.f;
    const float4* W4 = reinterpret_cast<const float4*>(W + tid * HID);
#pragma unroll 4
    for (int k4 = 0; k4 < HID / 4; k4++) {
        float4 w = W4[k4];
#pragma unroll
        for (int i = 0; i < TM; i++) {
            float4 xv = *reinterpret_cast<const float4*>(&Xs[i][k4 * 4]);
            acc[i] += xv.x * w.x + xv.y * w.y + xv.z * w.z + xv.w * w.w;
        }
    }
    float bb = b[tid];
    for (int i = 0; i < nrows; i++) g_x[(r0 + i) * HID + tid] = acc[i] + bb;
}

// ---------------- generic row-tiled GEMM (1 or 2 weight matrices) ----------------
__global__ __launch_bounds__(128) void k_gemm(int in_sel, int use_active, int relu_in, int maxtiles,
                                              const float* __restrict__ W0, const float* __restrict__ b0, int out_sel0,
                                              const float* __restrict__ W1, const float* __restrict__ b1, int out_sel1) {
    int cnt = use_active ? g_activeCount : g_totalEntries;
    int mat = blockIdx.x / maxtiles;
    int t = blockIdx.x - mat * maxtiles;
    int r0 = t * TM;
    if (r0 >= cnt) return;
    const float* W = mat ? W1 : W0;
    const float* b = mat ? b1 : b0;
    float* out = selArr(mat ? out_sel1 : out_sel0);
    const float* in = selArr(in_sel);
    int tid = threadIdx.x;
    int nrows = min(TM, cnt - r0);
    __shared__ __align__(16) float Xs[TM][HID];
#pragma unroll
    for (int i = 0; i < TM; i++) {
        float v = 0.f;
        if (i < nrows) v = in[(r0 + i) * HID + tid];
        if (relu_in) v = fmaxf(v, 0.f);
        Xs[i][tid] = v;
    }
    __syncthreads();
    float acc[TM];
#pragma unroll
    for (int i = 0; i < TM; i++) acc[i] = 0.f;
    const float4* W4 = reinterpret_cast<const float4*>(W + tid * HID);
#pragma unroll 4
    for (int k4 = 0; k4 < HID / 4; k4++) {
        float4 w = W4[k4];
#pragma unroll
        for (int i = 0; i < TM; i++) {
            float4 xv = *reinterpret_cast<const float4*>(&Xs[i][k4 * 4]);
            acc[i] += xv.x * w.x + xv.y * w.y + xv.z * w.z + xv.w * w.w;
        }
    }
    float bb = b ? b[tid] : 0.f;
    for (int i = 0; i < nrows; i++) out[(r0 + i) * HID + tid] = acc[i] + bb;
}

// ---------------- tfeat: relu(ts*W1+b1) @ W2.T + b2 per incident entry ----------------
__global__ __launch_bounds__(128) void k_tfeat(const float* __restrict__ ts,
                                               const float* __restrict__ W1, const float* __restrict__ b1,
                                               const float* __restrict__ W2, const float* __restrict__ b2) {
    int M = g_totalEntries;
    int r0 = blockIdx.x * TM;
    if (r0 >= M) return;
    int tid = threadIdx.x;
    int nrows = min(TM, M - r0);
    __shared__ __align__(16) float T1[TM][HID];
    float w1 = W1[tid], bb1 = b1[tid];
#pragma unroll
    for (int i = 0; i < TM; i++) {
        float v = 0.f;
        if (i < nrows) {
            float tv = ts[g_entryEdge[r0 + i]];
            v = fmaxf(tv * w1 + bb1, 0.f);
        }
        T1[i][tid] = v;
    }
    __syncthreads();
    float acc[TM];
#pragma unroll
    for (int i = 0; i < TM; i++) acc[i] = 0.f;
    const float4* W4 = reinterpret_cast<const float4*>(W2 + tid * HID);
#pragma unroll 4
    for (int k4 = 0; k4 < HID / 4; k4++) {
        float4 w = W4[k4];
#pragma unroll
        for (int i = 0; i < TM; i++) {
            float4 xv = *reinterpret_cast<const float4*>(&T1[i][k4 * 4]);
            acc[i] += xv.x * w.x + xv.y * w.y + xv.z * w.z + xv.w * w.w;
        }
    }
    float bb2 = b2[tid];
    for (int i = 0; i < nrows; i++) g_tfeat[(r0 + i) * HID + tid] = acc[i] + bb2;
}

// ---------------- per-target attention + output/op projections ----------------
__global__ __launch_bounds__(128) void k_attn(const int* __restrict__ tp,
                                              const float* __restrict__ Wq, const float* __restrict__ bq,
                                              const float* __restrict__ Wo, const float* __restrict__ bo,
                                              const float* __restrict__ Wop, const float* __restrict__ bop) {
    int u = blockIdx.x;
    int tid = threadIdx.x;
    int lane = tid & 31, h = tid >> 5;
    __shared__ __align__(16) float s_in[HID];
    __shared__ __align__(16) float s_q[HID];
    __shared__ __align__(16) float s_vec[HID];
    __shared__ float s_sc[NH][DEGCAP];
    int tgt = tp[u];
    int slot = g_node2slot[tgt];
    s_in[tid] = g_tf[slot * HID + tid];
    __syncthreads();
    // q = tf[target] @ Wq.T + bq
    {
        float acc = 0.f;
        const float4* W4 = reinterpret_cast<const float4*>(Wq + tid * HID);
#pragma unroll 4
        for (int k4 = 0; k4 < HID / 4; k4++) {
            float4 w = W4[k4];
            float4 xv = *reinterpret_cast<const float4*>(&s_in[k4 * 4]);
            acc += xv.x * w.x + xv.y * w.y + xv.z * w.z + xv.w * w.w;
        }
        s_q[tid] = acc + bq[tid];
    }
    __syncthreads();
    int deg = g_deg[u];
    int base = g_incBase[u];
    if (deg > 0) {
        const float scale = 0.17677669529663687f;  // 1/sqrt(32)
        float qv = s_q[h * DH + lane];
        for (int i = 0; i < deg; i++) {
            int m = base + i;
            int ns = g_node2slot[g_entryNbr[m]];
            float kk = g_Ak[ns * HID + h * DH + lane] + g_Bk[m * HID + h * DH + lane];
            float v = qv * kk;
#pragma unroll
            for (int o = 16; o > 0; o >>= 1) v += __shfl_xor_sync(0xffffffffu, v, o);
            if (lane == 0) s_sc[h][i] = v * scale;
        }
        __syncwarp();
        float mx = -1e30f;
        for (int i = lane; i < deg; i += 32) mx = fmaxf(mx, s_sc[h][i]);
#pragma unroll
        for (int o = 16; o > 0; o >>= 1) mx = fmaxf(mx, __shfl_xor_sync(0xffffffffu, mx, o));
        float ssum = 0.f;
        for (int i = lane; i < deg; i += 32) {
            float p = expf(s_sc[h][i] - mx);
            s_sc[h][i] = p;
            ssum += p;
        }
#pragma unroll
        for (int o = 16; o > 0; o >>= 1) ssum += __shfl_xor_sync(0xffffffffu, ssum, o);
        float inv = 1.f / ssum;
        __syncwarp();
        float oacc = 0.f;
        for (int i = 0; i < deg; i++) {
            int m = base + i;
            int ns = g_node2slot[g_entryNbr[m]];
            float vv = g_Av[ns * HID + h * DH + lane] + g_Bv[m * HID + h * DH + lane];
            oacc += s_sc[h][i] * inv * vv;
        }
        s_vec[h * DH + lane] = oacc;
        __syncthreads();
        float acc = 0.f;
        const float4* W4 = reinterpret_cast<const float4*>(Wo + tid * HID);
#pragma unroll 4
        for (int k4 = 0; k4 < HID / 4; k4++) {
            float4 w = W4[k4];
            float4 xv = *reinterpret_cast<const float4*>(&s_vec[k4 * 4]);
            acc += xv.x * w.x + xv.y * w.y + xv.z * w.z + xv.w * w.w;
        }
        float attn_v = acc + bo[tid];
        __syncthreads();
        s_vec[tid] = attn_v;
    } else {
        s_vec[tid] = s_in[tid];
    }
    __syncthreads();
    // agg = agg_in @ op_W.T + op_b -> x[slot]
    float acc = 0.f;
    const float4* W4 = reinterpret_cast<const float4*>(Wop + tid * HID);
#pragma unroll 4
    for (int k4 = 0; k4 < HID / 4; k4++) {
        float4 w = W4[k4];
        float4 xv = *reinterpret_cast<const float4*>(&s_vec[k4 * 4]);
        acc += xv.x * w.x + xv.y * w.y + xv.z * w.z + xv.w * w.w;
    }
    g_x[slot * HID + tid] = acc + bop[tid];
}

// ---------------- final: emb for both endpoints + link predictor ----------------
__global__ __launch_bounds__(128) void k_head(const int* __restrict__ tp,
                                              const float* __restrict__ o1W, const float* __restrict__ o1b,
                                              const float* __restrict__ o2W, const float* __restrict__ o2b,
                                              const float* __restrict__ l1W, const float* __restrict__ l1b,
                                              const float* __restrict__ l2W, const float* __restrict__ l2b,
                                              const float* __restrict__ l3W, const float* __restrict__ l3b,
                                              float* __restrict__ out) {
    int p = blockIdx.x;
    int tid = threadIdx.x;
    __shared__ __align__(16) float s_x[HID];
    __shared__ __align__(16) float s_h[HID];
    __shared__ __align__(16) float s_pair[2 * OUTD];
    __shared__ __align__(16) float s_z[HID];
    __shared__ float s_z2[OUTD];
    for (int side = 0; side < 2; side++) {
        int tgt = tp[2 * p + side];
        int slot = g_node2slot[tgt];
        s_x[tid] = fmaxf(g_x[slot * HID + tid], 0.f);
        __syncthreads();
        float acc = 0.f;
        const float4* W4 = reinterpret_cast<const float4*>(o1W + tid * HID);
#pragma unroll 4
        for (int k4 = 0; k4 < HID / 4; k4++) {
            float4 w = W4[k4];
            float4 xv = *reinterpret_cast<const float4*>(&s_x[k4 * 4]);
            acc += xv.x * w.x + xv.y * w.y + xv.z * w.z + xv.w * w.w;
        }
        s_h[tid] = fmaxf(acc + o1b[tid], 0.f);
        __syncthreads();
        if (tid < OUTD) {
            float a2 = 0.f;
            const float4* W24 = reinterpret_cast<const float4*>(o2W + tid * HID);
#pragma unroll 4
            for (int k4 = 0; k4 < HID / 4; k4++) {
                float4 w = W24[k4];
                float4 xv = *reinterpret_cast<const float4*>(&s_h[k4 * 4]);
                a2 += xv.x * w.x + xv.y * w.y + xv.z * w.z + xv.w * w.w;
            }
            s_pair[side * OUTD + tid] = a2 + o2b[tid];
        }
        __syncthreads();
    }
    // z1 = relu(pair @ l1W.T + b1)   (l1W: [HID][2*OUTD])
    {
        float acc = 0.f;
        const float4* W4 = reinterpret_cast<const float4*>(l1W + tid * (2 * OUTD));
#pragma unroll 4
        for (int k4 = 0; k4 < (2 * OUTD) / 4; k4++) {
            float4 w = W4[k4];
            float4 xv = *reinterpret_cast<const float4*>(&s_pair[k4 * 4]);
            acc += xv.x * w.x + xv.y * w.y + xv.z * w.z + xv.w * w.w;
        }
        s_z[tid] = fmaxf(acc + l1b[tid], 0.f);
    }
    __syncthreads();
    if (tid < OUTD) {
        float a = 0.f;
        const float4* W24 = reinterpret_cast<const float4*>(l2W + tid * HID);
#pragma unroll 4
        for (int k4 = 0; k4 < HID / 4; k4++) {
            float4 w = W24[k4];
            float4 xv = *reinterpret_cast<const float4*>(&s_z[k4 * 4]);
            a += xv.x * w.x + xv.y * w.y + xv.z * w.z + xv.w * w.w;
        }
        s_z2[tid] = fmaxf(a + l2b[tid], 0.f);
    }
    __syncthreads();
    if (tid == 0) {
        float a = 0.f;
        for (int k = 0; k < OUTD; k++) a += s_z2[k] * l3W[k];
        a += l3b[0];
        out[p] = 1.f / (1.f + expf(-a));
    }
}

// ---------------- launch ----------------
extern "C" void kernel_launch(void* const* d_in, const int* in_sizes, int n_in,
                              void* d_out, int out_size) {
    const float* nf    = (const float*)d_in[0];
    const int*   ei    = (const int*)d_in[1];
    const float* ets   = (const float*)d_in[2];
    const int*   tp    = (const int*)d_in[3];
    const float* in_W  = (const float*)d_in[4];
    const float* in_b  = (const float*)d_in[5];
    const float* te_W1 = (const float*)d_in[6];
    const float* te_b1 = (const float*)d_in[7];
    const float* te_W2 = (const float*)d_in[8];
    const float* te_b2 = (const float*)d_in[9];
    const float* aiW   = (const float*)d_in[10];
    const float* aib   = (const float*)d_in[11];
    const float* aoW   = (const float*)d_in[12];
    const float* aob   = (const float*)d_in[13];
    const float* ftW   = (const float*)d_in[14];
    const float* ftb   = (const float*)d_in[15];
    const float* opW   = (const float*)d_in[16];
    const float* opb   = (const float*)d_in[17];
    const float* o1W   = (const float*)d_in[18];
    const float* o1b   = (const float*)d_in[19];
    const float* o2W   = (const float*)d_in[20];
    const float* o2b   = (const float*)d_in[21];
    const float* l1W   = (const float*)d_in[22];
    const float* l1b   = (const float*)d_in[23];
    const float* l2W   = (const float*)d_in[24];
    const float* l2b   = (const float*)d_in[25];
    const float* l3W   = (const float*)d_in[26];
    const float* l3b   = (const float*)d_in[27];
    float* out = (float*)d_out;

    k_init<<<(NNODES + 255) / 256, 256>>>();
    k_build<<<UTOT, 256>>>(ei, tp);
    k_input<<<MAXT_A, HID>>>(nf, in_W, in_b);
    for (int l = 0; l < 2; l++) {
        const float* Wq = aiW + (size_t)l * 3 * HID * HID;
        const float* Wk = Wq + HID * HID;
        const float* Wv = Wk + HID * HID;
        const float* bq = aib + (size_t)l * 3 * HID;
        const float* bk = bq + HID;
        const float* bv = bk + HID;
        // tf = (relu?)x @ ft_W.T + ft_b
        k_gemm<<<MAXT_A, HID>>>(0, 1, (l == 1) ? 1 : 0, MAXT_A,
                                ftW + l * HID * HID, ftb + l * HID, 1,
                                nullptr, nullptr, 1);
        // Ak = tf @ Wk.T ; Av = tf @ Wv.T  (no bias)
        k_gemm<<<2 * MAXT_A, HID>>>(1, 1, 0, MAXT_A,
                                    Wk, nullptr, 2,
                                    Wv, nullptr, 3);
        // tfeat for incident entries
        k_tfeat<<<MAXT_M, HID>>>(ets, te_W1 + l * HID, te_b1 + l * HID,
                                 te_W2 + l * HID * HID, te_b2 + l * HID);
        // Bk = tfeat @ Wk.T + bk ; Bv = tfeat @ Wv.T + bv
        k_gemm<<<2 * MAXT_M, HID>>>(4, 0, 0, MAXT_M,
                                    Wk, bk, 5,
                                    Wv, bv, 6);
        // attention + out/op projections -> x[targets]
        k_attn<<<UTOT, HID>>>(tp, Wq, bq,
                              aoW + l * HID * HID, aob + l * HID,
                              opW + l * HID * HID, opb + l * HID);
    }
    k_head<<<NPAIRS, HID>>>(tp, o1W, o1b, o2W, o2b,
                            l1W, l1b, l2W, l2b, l3W, l3b, out);
}

// round 2
// speedup vs baseline: 1.2391x; 1.2391x over previous
#include <cuda_runtime.h>
#include <math.h>

#define NNODES 20000
#define NEDGES 50000
#define HID 128
#define OUTD 64
#define NPAIRS 128
#define UTOT 256
#define NH 4
#define DH 32
#define DEGCAP 64
#define MCAP (UTOT * DEGCAP)   /* 16384 */
#define ACAPN (UTOT + MCAP)    /* 16640 */
#define TM 8
#define NT_TILES ((ACAPN + TM - 1) / TM) /* 2080 */
#define NE_TILES ((MCAP + TM - 1) / TM)  /* 2048 */
#define NQ_TILES (UTOT / TM)             /* 32 */
#define BIGOWN 0x7fffffff

// ---------------- device scratch ----------------
__device__ int g_owner[NNODES];
__device__ int g_node2slot[NNODES];
__device__ int g_degRaw[UTOT];
__device__ int g_rawEdge[UTOT * DEGCAP];
__device__ int g_rawNbr[UTOT * DEGCAP];
__device__ int g_deg[UTOT];
__device__ int g_incBase[UTOT];
__device__ int g_tslot[UTOT];
__device__ int g_entryEdge[MCAP];
__device__ int g_entrySlot[MCAP];
__device__ int g_activeNodes[ACAPN];
__device__ int g_activeCount;
__device__ int g_totalEntries;

__device__ float g_x[ACAPN * HID];
__device__ float g_tf[ACAPN * HID];
__device__ float g_tfeat[MCAP * HID];
__device__ float g_K[MCAP * HID];
__device__ float g_V[MCAP * HID];
__device__ float g_q[UTOT * HID];
// transposed weights: 19 slots of HID*HID
// 0:in 1,2:ft 3,4:te2 5,6:q 7,8:k 9,10:v 11,12:ao 13,14:op 15:o1 16:o2(R64) 17:l1 18:l2(R64)
__device__ float g_WT[19 * HID * HID];

__device__ __forceinline__ const float* WT(int m) { return g_WT + m * HID * HID; }

__device__ __forceinline__ void ensure_slot(int n) {
    if (g_node2slot[n] == -1) {
        if (atomicCAS(&g_node2slot[n], -1, -2) == -1) {
            int s = atomicAdd(&g_activeCount, 1);
            g_activeNodes[s] = n;
            __threadfence();
            g_node2slot[n] = s;
        }
    }
}

// ---------------- init ----------------
__global__ void k_init() {
    int i = blockIdx.x * blockDim.x + threadIdx.x;
    if (i < NNODES) { g_owner[i] = BIGOWN; g_node2slot[i] = -1; }
    if (i < UTOT) g_degRaw[i] = 0;
    if (i == 0) { g_activeCount = 0; g_totalEntries = 0; }
}

// ---------------- weight transpose (coalesced-read) ----------------
__global__ __launch_bounds__(256) void k_transpose(
    const float* __restrict__ inW, const float* __restrict__ ftW,
    const float* __restrict__ teW2, const float* __restrict__ aiW,
    const float* __restrict__ aoW, const float* __restrict__ opW,
    const float* __restrict__ o1W, const float* __restrict__ o2W,
    const float* __restrict__ l1W, const float* __restrict__ l2W) {
    int m = blockIdx.x >> 2;        // matrix id 0..18
    int part = blockIdx.x & 3;      // quarter
    const float* src;
    int R = HID;
    switch (m) {
        case 0: src = inW; break;
        case 1: case 2: src = ftW + (m - 1) * HID * HID; break;
        case 3: case 4: src = teW2 + (m - 3) * HID * HID; break;
        case 5: case 6: src = aiW + (size_t)(m - 5) * 3 * HID * HID; break;
        case 7: case 8: src = aiW + (size_t)(m - 7) * 3 * HID * HID + HID * HID; break;
        case 9: case 10: src = aiW + (size_t)(m - 9) * 3 * HID * HID + 2 * HID * HID; break;
        case 11: case 12: src = aoW + (m - 11) * HID * HID; break;
        case 13: case 14: src = opW + (m - 13) * HID * HID; break;
        case 15: src = o1W; break;
        case 16: src = o2W; R = OUTD; break;
        case 17: src = l1W; break;
        default: src = l2W; R = OUTD; break;
    }
    float* dst = g_WT + m * HID * HID;
    int total = R * HID;
    int chunk = (total + 3) / 4;
    for (int idx = part * chunk + threadIdx.x; idx < min((part + 1) * chunk, total); idx += 256) {
        int r = idx >> 7;       // /HID
        int c = idx & (HID - 1);
        dst[c * R + r] = src[idx];
    }
}

// ---------------- mark targets ----------------
__global__ void k_mark(const int* __restrict__ tp) {
    int u = threadIdx.x;
    atomicMin(&g_owner[tp[u]], u);
}

// ---------------- single pass over edges ----------------
__global__ __launch_bounds__(256) void k_scan(const int* __restrict__ ei) {
    int e = blockIdx.x * 256 + threadIdx.x;
    if (e >= NEDGES) return;
    int s = ei[e], d = ei[NEDGES + e];
    int os = g_owner[s];
    if (os != BIGOWN) {
        int p = atomicAdd(&g_degRaw[os], 1);
        if (p < DEGCAP) { g_rawEdge[os * DEGCAP + p] = e; g_rawNbr[os * DEGCAP + p] = d; }
    }
    if (s != d) {
        int od = g_owner[d];
        if (od != BIGOWN) {
            int p = atomicAdd(&g_degRaw[od], 1);
            if (p < DEGCAP) { g_rawEdge[od * DEGCAP + p] = e; g_rawNbr[od * DEGCAP + p] = s; }
        }
    }
}

// ---------------- per-owner sort by edge id (determinism) ----------------
__global__ void k_sort(const int* __restrict__ tp) {
    int u = blockIdx.x;
    if (threadIdx.x != 0) return;
    if (g_owner[tp[u]] != u) return;  // only owners sort their region
    int d = min(g_degRaw[u], DEGCAP);
    int* E = g_rawEdge + u * DEGCAP;
    int* Nb = g_rawNbr + u * DEGCAP;
    for (int i = 1; i < d; i++) {
        int e = E[i], n = Nb[i];
        int j = i - 1;
        while (j >= 0 && E[j] > e) { E[j + 1] = E[j]; Nb[j + 1] = Nb[j]; j--; }
        E[j + 1] = e; Nb[j + 1] = n;
    }
}

// ---------------- compact + slot assignment (1 block) ----------------
__global__ __launch_bounds__(256) void k_compact(const int* __restrict__ tp) {
    __shared__ int s_len[UTOT];
    __shared__ int s_base[UTOT];
    __shared__ int s_tot;
    int u = threadIdx.x;
    int tgt = tp[u];
    int own = g_owner[tgt];
    int d = min(g_degRaw[own], DEGCAP);
    s_len[u] = (own == u) ? d : 0;
    __syncthreads();
    if (u == 0) {
        int acc = 0;
        for (int i = 0; i < UTOT; i++) { s_base[i] = acc; acc += s_len[i]; }
        s_tot = acc;
        g_totalEntries = acc;
    }
    __syncthreads();
    g_deg[u] = d;
    g_incBase[u] = s_base[own];
    ensure_slot(tgt);
    if (own == u) {
        int b = s_base[u];
        for (int i = 0; i < d; i++) {
            int nb = g_rawNbr[u * DEGCAP + i];
            g_entryEdge[b + i] = g_rawEdge[u * DEGCAP + i];
            g_entrySlot[b + i] = nb;  // temp: node id
            ensure_slot(nb);
        }
    }
    __syncthreads();
    g_tslot[u] = g_node2slot[tgt];
    int tot = s_tot;
    for (int j = u; j < tot; j += UTOT)
        g_entrySlot[j] = g_node2slot[g_entrySlot[j]];
}

// ---------------- TM-row x [HID->HID] gemm tile core (coalesced WT) ----------------
__device__ __forceinline__ void tile_gemm(const float (*Xs)[HID], int nrows,
                                          const float* __restrict__ Wt,
                                          const float* __restrict__ b,
                                          float* __restrict__ out, int row0, int tid) {
    float acc[TM];
#pragma unroll
    for (int i = 0; i < TM; i++) acc[i] = 0.f;
#pragma unroll 8
    for (int k = 0; k < HID; k++) {
        float w = Wt[k * HID + tid];
#pragma unroll
        for (int i = 0; i < TM; i++) acc[i] += Xs[i][k] * w;
    }
    float bb = b ? b[tid] : 0.f;
    for (int i = 0; i < nrows; i++) out[(size_t)(row0 + i) * HID + tid] = acc[i] + bb;
}

// ---------------- input projection ----------------
__global__ __launch_bounds__(128) void k_input(const float* __restrict__ nf,
                                               const float* __restrict__ b) {
    int A = g_activeCount;
    int r0 = blockIdx.x * TM;
    if (r0 >= A) return;
    int tid = threadIdx.x;
    int nrows = min(TM, A - r0);
    __shared__ float Xs[TM][HID];
#pragma unroll
    for (int i = 0; i < TM; i++) {
        float v = 0.f;
        if (i < nrows) v = nf[(size_t)g_activeNodes[r0 + i] * HID + tid];
        Xs[i][tid] = v;
    }
    __syncthreads();
    tile_gemm(Xs, nrows, WT(0), b, g_x, r0, tid);
}

// ---------------- layer kernel A: tf (nodes) + tfeat (entries) ----------------
__global__ __launch_bounds__(128) void k_layerA(int l, const float* __restrict__ ts,
                                                const float* __restrict__ ftb,
                                                const float* __restrict__ teW1,
                                                const float* __restrict__ teb1,
                                                const float* __restrict__ teb2) {
    int tid = threadIdx.x;
    __shared__ float Xs[TM][HID];
    if (blockIdx.x < NT_TILES) {
        int A = g_activeCount;
        int r0 = blockIdx.x * TM;
        if (r0 >= A) return;
        int nrows = min(TM, A - r0);
#pragma unroll
        for (int i = 0; i < TM; i++) {
            float v = 0.f;
            if (i < nrows) v = g_x[(size_t)(r0 + i) * HID + tid];
            if (l) v = fmaxf(v, 0.f);
            Xs[i][tid] = v;
        }
        __syncthreads();
        tile_gemm(Xs, nrows, WT(1 + l), ftb, g_tf, r0, tid);
    } else {
        int M = g_totalEntries;
        int r0 = (blockIdx.x - NT_TILES) * TM;
        if (r0 >= M) return;
        int nrows = min(TM, M - r0);
        float w1 = teW1[tid], bb1 = teb1[tid];
#pragma unroll
        for (int i = 0; i < TM; i++) {
            float v = 0.f;
            if (i < nrows) v = fmaxf(ts[g_entryEdge[r0 + i]] * w1 + bb1, 0.f);
            Xs[i][tid] = v;
        }
        __syncthreads();
        tile_gemm(Xs, nrows, WT(3 + l), teb2, g_tfeat, r0, tid);
    }
}

// ---------------- layer kernel B: K,V (entries) + q (targets) ----------------
__global__ __launch_bounds__(128) void k_layerB(int l,
                                                const float* __restrict__ bq,
                                                const float* __restrict__ bk,
                                                const float* __restrict__ bv) {
    int tid = threadIdx.x;
    __shared__ float Xs[TM][HID];
    if (blockIdx.x < NE_TILES) {
        int M = g_totalEntries;
        int r0 = blockIdx.x * TM;
        if (r0 >= M) return;
        int nrows = min(TM, M - r0);
#pragma unroll
        for (int i = 0; i < TM; i++) {
            float v = 0.f;
            if (i < nrows)
                v = g_tf[(size_t)g_entrySlot[r0 + i] * HID + tid] +
                    g_tfeat[(size_t)(r0 + i) * HID + tid];
            Xs[i][tid] = v;
        }
        __syncthreads();
        tile_gemm(Xs, nrows, WT(7 + l), bk, g_K, r0, tid);
        tile_gemm(Xs, nrows, WT(9 + l), bv, g_V, r0, tid);
    } else {
        int r0 = (blockIdx.x - NE_TILES) * TM;
#pragma unroll
        for (int i = 0; i < TM; i++)
            Xs[i][tid] = g_tf[(size_t)g_tslot[r0 + i] * HID + tid];
        __syncthreads();
        tile_gemm(Xs, TM, WT(5 + l), bq, g_q, r0, tid);
    }
}

// ---------------- layer kernel C: attention + out/op projection ----------------
__global__ __launch_bounds__(128) void k_layerC(int l,
                                                const float* __restrict__ bo,
                                                const float* __restrict__ bop) {
    int u = blockIdx.x;
    int tid = threadIdx.x;
    int lane = tid & 31, h = tid >> 5;
    __shared__ float s_vec[HID];
    __shared__ float s_out[HID];
    __shared__ float s_sc[NH][DEGCAP];
    int deg = g_deg[u];
    int base = g_incBase[u];
    int slot = g_tslot[u];
    if (deg > 0) {
        const float scale = 0.17677669529663687f;  // 1/sqrt(32)
        float qv = g_q[u * HID + tid];
        for (int i = 0; i < deg; i++) {
            float kk = g_K[(size_t)(base + i) * HID + tid];
            float v = qv * kk;
#pragma unroll
            for (int o = 16; o > 0; o >>= 1) v += __shfl_xor_sync(0xffffffffu, v, o);
            if (lane == 0) s_sc[h][i] = v * scale;
        }
        __syncwarp();
        float mx = -1e30f;
        for (int i = lane; i < deg; i += 32) mx = fmaxf(mx, s_sc[h][i]);
#pragma unroll
        for (int o = 16; o > 0; o >>= 1) mx = fmaxf(mx, __shfl_xor_sync(0xffffffffu, mx, o));
        float ssum = 0.f;
        for (int i = lane; i < deg; i += 32) {
            float p = expf(s_sc[h][i] - mx);
            s_sc[h][i] = p;
            ssum += p;
        }
#pragma unroll
        for (int o = 16; o > 0; o >>= 1) ssum += __shfl_xor_sync(0xffffffffu, ssum, o);
        float inv = 1.f / ssum;
        __syncwarp();
        float oacc = 0.f;
        for (int i = 0; i < deg; i++)
            oacc += s_sc[h][i] * inv * g_V[(size_t)(base + i) * HID + tid];
        s_vec[tid] = oacc;
        __syncthreads();
        // attn_out gemv
        const float* Wt = WT(11 + l);
        float acc = 0.f;
#pragma unroll 8
        for (int k = 0; k < HID; k++) acc += s_vec[k] * Wt[k * HID + tid];
        float attn_v = acc + bo[tid];
        __syncthreads();
        s_out[tid] = attn_v;
    } else {
        s_out[tid] = g_tf[(size_t)slot * HID + tid];
    }
    __syncthreads();
    const float* Wt = WT(13 + l);
    float acc = 0.f;
#pragma unroll 8
    for (int k = 0; k < HID; k++) acc += s_out[k] * Wt[k * HID + tid];
    g_x[(size_t)slot * HID + tid] = acc + bop[tid];
}

// ---------------- head: emb + link predictor ----------------
__global__ __launch_bounds__(128) void k_head(const float* __restrict__ o1b,
                                              const float* __restrict__ o2b,
                                              const float* __restrict__ l1b,
                                              const float* __restrict__ l2b,
                                              const float* __restrict__ l3W,
                                              const float* __restrict__ l3b,
                                              float* __restrict__ out) {
    int p = blockIdx.x;
    int tid = threadIdx.x;
    __shared__ float s_x[HID];
    __shared__ float s_h[HID];
    __shared__ float s_pair[2 * OUTD];
    __shared__ float s_z[HID];
    __shared__ float s_z2[OUTD];
    for (int side = 0; side < 2; side++) {
        int slot = g_tslot[2 * p + side];
        s_x[tid] = fmaxf(g_x[(size_t)slot * HID + tid], 0.f);
        __syncthreads();
        const float* W1t = WT(15);
        float acc = 0.f;
#pragma unroll 8
        for (int k = 0; k < HID; k++) acc += s_x[k] * W1t[k * HID + tid];
        s_h[tid] = fmaxf(acc + o1b[tid], 0.f);
        __syncthreads();
        if (tid < OUTD) {
            const float* W2t = WT(16);
            float a2 = 0.f;
#pragma unroll 8
            for (int k = 0; k < HID; k++) a2 += s_h[k] * W2t[k * OUTD + tid];
            s_pair[side * OUTD + tid] = a2 + o2b[tid];
        }
        __syncthreads();
    }
    {
        const float* Wt = WT(17);
        float acc = 0.f;
#pragma unroll 8
        for (int k = 0; k < 2 * OUTD; k++) acc += s_pair[k] * Wt[k * HID + tid];
        s_z[tid] = fmaxf(acc + l1b[tid], 0.f);
    }
    __syncthreads();
    if (tid < OUTD) {
        const float* Wt = WT(18);
        float a = 0.f;
#pragma unroll 8
        for (int k = 0; k < HID; k++) a += s_z[k] * Wt[k * OUTD + tid];
        s_z2[tid] = fmaxf(a + l2b[tid], 0.f);
    }
    __syncthreads();
    if (tid == 0) {
        float a = 0.f;
        for (int k = 0; k < OUTD; k++) a += s_z2[k] * l3W[k];
        a += l3b[0];
        out[p] = 1.f / (1.f + expf(-a));
    }
}

// ---------------- launch ----------------
extern "C" void kernel_launch(void* const* d_in, const int* in_sizes, int n_in,
                              void* d_out, int out_size) {
    const float* nf    = (const float*)d_in[0];
    const int*   ei    = (const int*)d_in[1];
    const float* ets   = (const float*)d_in[2];
    const int*   tp    = (const int*)d_in[3];
    const float* in_W  = (const float*)d_in[4];
    const float* in_b  = (const float*)d_in[5];
    const float* te_W1 = (const float*)d_in[6];
    const float* te_b1 = (const float*)d_in[7];
    const float* te_W2 = (const float*)d_in[8];
    const float* te_b2 = (const float*)d_in[9];
    const float* aiW   = (const float*)d_in[10];
    const float* aib   = (const float*)d_in[11];
    const float* aoW   = (const float*)d_in[12];
    const float* aob   = (const float*)d_in[13];
    const float* ftW   = (const float*)d_in[14];
    const float* ftb   = (const float*)d_in[15];
    const float* opW   = (const float*)d_in[16];
    const float* opb   = (const float*)d_in[17];
    const float* o1W   = (const float*)d_in[18];
    const float* o1b   = (const float*)d_in[19];
    const float* o2W   = (const float*)d_in[20];
    const float* o2b   = (const float*)d_in[21];
    const float* l1W   = (const float*)d_in[22];
    const float* l1b   = (const float*)d_in[23];
    const float* l2W   = (const float*)d_in[24];
    const float* l2b   = (const float*)d_in[25];
    const float* l3W   = (const float*)d_in[26];
    const float* l3b   = (const float*)d_in[27];
    float* out = (float*)d_out;

    k_init<<<(NNODES + 255) / 256, 256>>>();
    k_transpose<<<19 * 4, 256>>>(in_W, ftW, te_W2, aiW, aoW, opW, o1W, o2W, l1W, l2W);
    k_mark<<<1, UTOT>>>(tp);
    k_scan<<<(NEDGES + 255) / 256, 256>>>(ei);
    k_sort<<<UTOT, 32>>>(tp);
    k_compact<<<1, UTOT>>>(tp);
    k_input<<<NT_TILES, 128>>>(nf, in_b);
    for (int l = 0; l < 2; l++) {
        const float* bq = aib + (size_t)l * 3 * HID;
        k_layerA<<<NT_TILES + NE_TILES, 128>>>(l, ets, ftb + l * HID,
                                               te_W1 + l * HID, te_b1 + l * HID,
                                               te_b2 + l * HID);
        k_layerB<<<NE_TILES + NQ_TILES, 128>>>(l, bq, bq + HID, bq + 2 * HID);
        k_layerC<<<UTOT, 128>>>(l, aob + l * HID, opb + l * HID);
    }
    k_head<<<NPAIRS, 128>>>(o1b, o2b, l1b, l2b, l3W, l3b, out);
}

// round 3
// speedup vs baseline: 1.5474x; 1.2488x over previous
#include <cuda_runtime.h>
#include <math.h>

#define NNODES 20000
#define NEDGES 50000
#define HID 128
#define OUTD 64
#define NPAIRS 128
#define UTOT 256
#define DEGCAP 64
#define MCAP (UTOT * DEGCAP)   /* 16384 */
#define ACAPN (UTOT + MCAP)    /* 16640 */
#define TM 8
#define NB 296
#define NTHREADS 256
#define NUNITS (2 * NB)
#define ENCMAX 0x7fffffff

// ---------------- device scratch (zero-init == clean state) ----------------
__device__ int g_owner[NNODES];      // 0 = unmarked, else ENCMAX - u
__device__ int g_node2slot[NNODES];  // 0 = none, -1 = lock, else slot+1
__device__ int g_degRaw[UTOT];
__device__ int g_rawEdge[MCAP];
__device__ int g_rawNbr[MCAP];
__device__ int g_srtEdge[MCAP];
__device__ int g_srtNbr[MCAP];
__device__ int g_deg[UTOT];
__device__ int g_incBase[UTOT];
__device__ int g_tslot[UTOT];
__device__ int g_entryEdge[MCAP];
__device__ int g_entrySlot[MCAP];
__device__ int g_activeNodes[ACAPN];
__device__ int g_activeCount;
__device__ int g_totalEntries;
__device__ unsigned g_barArrive;
__device__ unsigned g_barGen;

__device__ float g_x[ACAPN * HID];
__device__ float g_tf[ACAPN * HID];
__device__ float g_tfeat[MCAP * HID];
__device__ float g_K[MCAP * HID];
__device__ float g_V[MCAP * HID];
__device__ float g_q[UTOT * HID];
// transposed weights: 0:in 1,2:ft 3,4:te2 5,6:q 7,8:k 9,10:v 11,12:ao 13,14:op
// 15:o1 16:o2(R=64) 17:l1 18:l2(R=64)
__device__ float g_WT[19 * HID * HID];

__device__ __forceinline__ const float* WT(int m) { return g_WT + m * HID * HID; }

// ---------------- grid barrier (all NB blocks co-resident) ----------------
__device__ __forceinline__ void gsync(unsigned& gen) {
    __syncthreads();
    if (threadIdx.x == 0) {
        __threadfence();
        gen++;
        unsigned old = atomicInc(&g_barArrive, NB - 1u);
        if (old == NB - 1u) {
            atomicAdd(&g_barGen, 1u);
        } else {
            while (atomicAdd(&g_barGen, 0u) < gen) __nanosleep(32);
        }
        __threadfence();
    }
    __syncthreads();
}

// 128-thread unit barrier (named barrier, two units per block)
__device__ __forceinline__ void usync(int unit) {
    asm volatile("bar.sync %0, 128;" ::"r"(unit + 1) : "memory");
}

__device__ __forceinline__ void ensure_slot(int n) {
    if (g_node2slot[n] == 0) {
        if (atomicCAS(&g_node2slot[n], 0, -1) == 0) {
            int s = atomicAdd(&g_activeCount, 1);
            g_activeNodes[s] = n;
            __threadfence();
            g_node2slot[n] = s + 1;
        }
    }
}

// Xs: TM x HID in shared; Wt: [k][o]; out[row][o]
__device__ __forceinline__ void tile_compute(const float* Xs, int nrows,
                                             const float* __restrict__ Wt,
                                             const float* __restrict__ b,
                                             float* __restrict__ out, int row0, int ut) {
    float acc[TM];
#pragma unroll
    for (int i = 0; i < TM; i++) acc[i] = 0.f;
#pragma unroll 8
    for (int k = 0; k < HID; k++) {
        float w = Wt[k * HID + ut];
#pragma unroll
        for (int i = 0; i < TM; i++) acc[i] += Xs[i * HID + k] * w;
    }
    float bb = b ? b[ut] : 0.f;
    for (int i = 0; i < nrows; i++) out[(size_t)(row0 + i) * HID + ut] = acc[i] + bb;
}

__global__ __launch_bounds__(NTHREADS, 2) void k_main(
    const float* __restrict__ nf, const int* __restrict__ ei,
    const float* __restrict__ ets, const int* __restrict__ tp,
    const float* __restrict__ inW, const float* __restrict__ inb,
    const float* __restrict__ teW1, const float* __restrict__ teb1,
    const float* __restrict__ teW2, const float* __restrict__ teb2,
    const float* __restrict__ aiW, const float* __restrict__ aib,
    const float* __restrict__ aoW, const float* __restrict__ aob,
    const float* __restrict__ ftW, const float* __restrict__ ftb,
    const float* __restrict__ opW, const float* __restrict__ opb,
    const float* __restrict__ o1W, const float* __restrict__ o1b,
    const float* __restrict__ o2W, const float* __restrict__ o2b,
    const float* __restrict__ l1W, const float* __restrict__ l1b,
    const float* __restrict__ l2W, const float* __restrict__ l2b,
    const float* __restrict__ l3W, const float* __restrict__ l3b,
    float* __restrict__ out) {
    __shared__ __align__(16) float sX[2][TM * HID];  // 8KB (also sort/transpose/head scratch)
    __shared__ __align__(16) float sAux[2][512];     // 4KB (attn scratch)
    int tid = threadIdx.x;
    int unit = tid >> 7;
    int ut = tid & 127;
    int bid = blockIdx.x;
    unsigned gen = 0;
    if (tid == 0) gen = atomicAdd(&g_barGen, 0u);

    // ===== P0: weight transpose (jobs 0..303) + mark targets (job 304) =====
    for (int job = bid; job < 305; job += NB) {
        if (job < 304) {
            int m = job >> 4, t = job & 15;
            const float* src;
            int R = HID;
            switch (m) {
                case 0: src = inW; break;
                case 1: case 2: src = ftW + (size_t)(m - 1) * HID * HID; break;
                case 3: case 4: src = teW2 + (size_t)(m - 3) * HID * HID; break;
                case 5: case 6: src = aiW + (size_t)(m - 5) * 3 * HID * HID; break;
                case 7: case 8: src = aiW + (size_t)(m - 7) * 3 * HID * HID + HID * HID; break;
                case 9: case 10: src = aiW + (size_t)(m - 9) * 3 * HID * HID + 2 * HID * HID; break;
                case 11: case 12: src = aoW + (size_t)(m - 11) * HID * HID; break;
                case 13: case 14: src = opW + (size_t)(m - 13) * HID * HID; break;
                case 15: src = o1W; break;
                case 16: src = o2W; R = OUTD; break;
                case 17: src = l1W; break;
                default: src = l2W; R = OUTD; break;
            }
            int tr = t >> 2, tc = t & 3;
            if (tr * 32 < R) {
                float* sh = &sX[0][0];  // 32x33 tile (1056 floats, fits 2048)
                int x = tid & 31, y0 = tid >> 5;
                float* dst = g_WT + (size_t)m * HID * HID;
#pragma unroll
                for (int k = 0; k < 4; k++) {
                    int y = y0 + 8 * k;
                    sh[y * 33 + x] = src[(size_t)(tr * 32 + y) * HID + tc * 32 + x];
                }
                __syncthreads();
#pragma unroll
                for (int k = 0; k < 4; k++) {
                    int y = y0 + 8 * k;
                    dst[(size_t)(tc * 32 + y) * R + tr * 32 + x] = sh[x * 33 + y];
                }
                __syncthreads();
            }
        } else if (tid < UTOT) {
            atomicMax(&g_owner[tp[tid]], ENCMAX - tid);
        }
    }
    gsync(gen);

    // ===== P1: edge scan =====
    for (int e = bid * NTHREADS + tid; e < NEDGES; e += NB * NTHREADS) {
        int s = ei[e], d = ei[NEDGES + e];
        int es = g_owner[s];
        if (es) {
            int u = ENCMAX - es;
            int p = atomicAdd(&g_degRaw[u], 1);
            if (p < DEGCAP) { g_rawEdge[u * DEGCAP + p] = e; g_rawNbr[u * DEGCAP + p] = d; }
        }
        if (s != d) {
            int ed = g_owner[d];
            if (ed) {
                int u = ENCMAX - ed;
                int p = atomicAdd(&g_degRaw[u], 1);
                if (p < DEGCAP) { g_rawEdge[u * DEGCAP + p] = e; g_rawNbr[u * DEGCAP + p] = s; }
            }
        }
    }
    gsync(gen);

    // ===== P2: sort (warp/target) + prefix (block 32) + ensure_slot (rest) =====
    if (bid < 32) {
        int wid = tid >> 5, lane = tid & 31;
        int u = bid * 8 + wid;
        if (g_owner[tp[u]] == ENCMAX - u) {
            int d = min(g_degRaw[u], DEGCAP);
            int* sE = ((int*)&sX[0][0]) + wid * 128;
            int* sN = sE + 64;
            for (int i = lane; i < d; i += 32) {
                sE[i] = g_rawEdge[u * DEGCAP + i];
                sN[i] = g_rawNbr[u * DEGCAP + i];
            }
            __syncwarp();
            for (int i = lane; i < d; i += 32) {
                int key = sE[i], nb = sN[i], rank = 0;
                for (int j = 0; j < d; j++) rank += (sE[j] < key);
                g_srtEdge[u * DEGCAP + rank] = key;
                g_srtNbr[u * DEGCAP + rank] = nb;
            }
        }
    } else if (bid == 32) {
        int* lens = (int*)&sX[0][0];
        int* excl = lens + 256;
        int* parts = excl + 256;
        int* poff = parts + 8;
        int u = tid;
        int own = ENCMAX - g_owner[tp[u]];
        int len = (own == u) ? min(g_degRaw[u], DEGCAP) : 0;
        lens[u] = len;
        int lane = tid & 31, wid = tid >> 5;
        int v = len;
#pragma unroll
        for (int off = 1; off < 32; off <<= 1) {
            int n = __shfl_up_sync(0xffffffffu, v, off);
            if (lane >= off) v += n;
        }
        if (lane == 31) parts[wid] = v;
        __syncthreads();
        if (tid == 0) {
            int a = 0;
            for (int w = 0; w < 8; w++) { poff[w] = a; a += parts[w]; }
            g_totalEntries = a;
        }
        __syncthreads();
        excl[u] = v - len + poff[wid];
        __syncthreads();
        g_deg[u] = min(g_degRaw[own], DEGCAP);
        g_incBase[u] = excl[own];
    } else {
        for (int idx = (bid - 33) * NTHREADS + tid; idx < UTOT + MCAP;
             idx += (NB - 33) * NTHREADS) {
            if (idx < UTOT) {
                ensure_slot(tp[idx]);
            } else {
                int r = idx - UTOT;
                int u = r >> 6, i = r & 63;
                if (i < min(g_degRaw[u], DEGCAP)) ensure_slot(g_rawNbr[u * DEGCAP + i]);
            }
        }
    }
    gsync(gen);

    // ===== P3: entry compaction + tslot (last block) | input projection (rest) =====
    if (bid == NB - 1) {
        for (int idx = tid; idx < UTOT + MCAP; idx += NTHREADS) {
            if (idx < UTOT) {
                g_tslot[idx] = g_node2slot[tp[idx]] - 1;
            } else {
                int r = idx - UTOT;
                int u = r >> 6, i = r & 63;
                if (g_owner[tp[u]] == ENCMAX - u && i < g_deg[u]) {
                    int b = g_incBase[u] + i;
                    g_entryEdge[b] = g_srtEdge[u * DEGCAP + i];
                    g_entrySlot[b] = g_node2slot[g_srtNbr[u * DEGCAP + i]] - 1;
                }
            }
        }
    } else {
        int A = g_activeCount;
        int NT = (A + TM - 1) / TM;
        for (int uid = bid * 2 + unit; uid < NT; uid += (NB - 1) * 2) {
            int r0 = uid * TM;
            int nrows = min(TM, A - r0);
            float* Xs = sX[unit];
#pragma unroll
            for (int i = 0; i < TM; i++) {
                float v = 0.f;
                if (i < nrows) v = nf[(size_t)g_activeNodes[r0 + i] * HID + ut];
                Xs[i * HID + ut] = v;
            }
            usync(unit);
            tile_compute(Xs, nrows, WT(0), inb, g_x, r0, ut);
            usync(unit);
        }
    }
    gsync(gen);

    // ===== layers =====
    for (int l = 0; l < 2; l++) {
        int A = g_activeCount, M = g_totalEntries;
        int NT = (A + TM - 1) / TM, NE = (M + TM - 1) / TM;
        const float* teW1l = teW1 + l * HID;
        const float* teb1l = teb1 + l * HID;
        const float* teb2l = teb2 + l * HID;
        const float* ftbl = ftb + l * HID;
        const float* bq = aib + (size_t)l * 3 * HID;
        const float* bk = bq + HID;
        const float* bv = bq + 2 * HID;
        const float* bo = aob + l * HID;
        const float* bop = opb + l * HID;

        // ---- A: tf (actives) + tfeat (entries) ----
        for (int job = bid * 2 + unit; job < NT + NE; job += NUNITS) {
            float* Xs = sX[unit];
            if (job < NT) {
                int r0 = job * TM;
                int nrows = min(TM, A - r0);
#pragma unroll
                for (int i = 0; i < TM; i++) {
                    float v = 0.f;
                    if (i < nrows) v = g_x[(size_t)(r0 + i) * HID + ut];
                    if (l) v = fmaxf(v, 0.f);
                    Xs[i * HID + ut] = v;
                }
                usync(unit);
                tile_compute(Xs, nrows, WT(1 + l), ftbl, g_tf, r0, ut);
            } else {
                int r0 = (job - NT) * TM;
                int nrows = min(TM, M - r0);
                float w1 = teW1l[ut], b1 = teb1l[ut];
#pragma unroll
                for (int i = 0; i < TM; i++) {
                    float v = 0.f;
                    if (i < nrows) v = fmaxf(ets[g_entryEdge[r0 + i]] * w1 + b1, 0.f);
                    Xs[i * HID + ut] = v;
                }
                usync(unit);
                tile_compute(Xs, nrows, WT(3 + l), teb2l, g_tfeat, r0, ut);
            }
            usync(unit);
        }
        gsync(gen);

        // ---- B: K, V (entries) + q (targets) ----
        int NQ = UTOT / TM;
        for (int job = bid * 2 + unit; job < 2 * NE + NQ; job += NUNITS) {
            float* Xs = sX[unit];
            if (job < 2 * NE) {
                int isV = (job >= NE);
                int r0 = (isV ? job - NE : job) * TM;
                int nrows = min(TM, M - r0);
#pragma unroll
                for (int i = 0; i < TM; i++) {
                    float v = 0.f;
                    if (i < nrows)
                        v = g_tf[(size_t)g_entrySlot[r0 + i] * HID + ut] +
                            g_tfeat[(size_t)(r0 + i) * HID + ut];
                    Xs[i * HID + ut] = v;
                }
                usync(unit);
                if (isV) tile_compute(Xs, nrows, WT(9 + l), bv, g_V, r0, ut);
                else     tile_compute(Xs, nrows, WT(7 + l), bk, g_K, r0, ut);
            } else {
                int r0 = (job - 2 * NE) * TM;
#pragma unroll
                for (int i = 0; i < TM; i++)
                    Xs[i * HID + ut] = g_tf[(size_t)g_tslot[r0 + i] * HID + ut];
                usync(unit);
                tile_compute(Xs, TM, WT(5 + l), bq, g_q, r0, ut);
            }
            usync(unit);
        }
        gsync(gen);

        // ---- C: attention + out/op projection ----
        for (int u = bid * 2 + unit; u < UTOT; u += NUNITS) {
            float* sc = sAux[unit];       // [4][64]
            float* vec = sc + 256;        // 128
            float* sout = vec + 128;      // 128
            int lane = ut & 31, h = ut >> 5;
            int deg = g_deg[u];
            int base = g_incBase[u];
            int slot = g_tslot[u];
            if (deg > 0) {
                const float scale = 0.17677669529663687f;  // 1/sqrt(32)
                float qv = g_q[u * HID + ut];
                for (int i = 0; i < deg; i++) {
                    float v = qv * g_K[(size_t)(base + i) * HID + ut];
#pragma unroll
                    for (int o = 16; o > 0; o >>= 1) v += __shfl_xor_sync(0xffffffffu, v, o);
                    if (lane == 0) sc[h * 64 + i] = v * scale;
                }
                __syncwarp();
                float mx = -1e30f;
                for (int i = lane; i < deg; i += 32) mx = fmaxf(mx, sc[h * 64 + i]);
#pragma unroll
                for (int o = 16; o > 0; o >>= 1) mx = fmaxf(mx, __shfl_xor_sync(0xffffffffu, mx, o));
                float ssum = 0.f;
                for (int i = lane; i < deg; i += 32) {
                    float p = expf(sc[h * 64 + i] - mx);
                    sc[h * 64 + i] = p;
                    ssum += p;
                }
#pragma unroll
                for (int o = 16; o > 0; o >>= 1) ssum += __shfl_xor_sync(0xffffffffu, ssum, o);
                float inv = 1.f / ssum;
                __syncwarp();
                float oacc = 0.f;
                for (int i = 0; i < deg; i++)
                    oacc += sc[h * 64 + i] * inv * g_V[(size_t)(base + i) * HID + ut];
                vec[ut] = oacc;
                usync(unit);
                const float* Wt = WT(11 + l);
                float acc = 0.f;
#pragma unroll 8
                for (int k = 0; k < HID; k++) acc += vec[k] * Wt[k * HID + ut];
                float attn_v = acc + bo[ut];
                usync(unit);
                sout[ut] = attn_v;
            } else {
                sout[ut] = g_tf[(size_t)slot * HID + ut];
            }
            usync(unit);
            const float* Wt = WT(13 + l);
            float acc = 0.f;
#pragma unroll 8
            for (int k = 0; k < HID; k++) acc += sout[k] * Wt[k * HID + ut];
            g_x[(size_t)slot * HID + ut] = acc + bop[ut];
            usync(unit);
        }
        gsync(gen);
    }

    // ===== P10: head (blocks 0..63) | cleanup (blocks 64..) =====
    if (bid < 64) {
        for (int p = bid * 2 + unit; p < NPAIRS; p += 128) {
            float* sx = sX[unit];
            float* shh = sx + 128;
            float* pair = sx + 256;
            float* zz = sx + 384;
            float* z2 = sx + 512;
            for (int side = 0; side < 2; side++) {
                int slot = g_tslot[2 * p + side];
                sx[ut] = fmaxf(g_x[(size_t)slot * HID + ut], 0.f);
                usync(unit);
                const float* W1t = WT(15);
                float acc = 0.f;
#pragma unroll 8
                for (int k = 0; k < HID; k++) acc += sx[k] * W1t[k * HID + ut];
                float hv = fmaxf(acc + o1b[ut], 0.f);
                usync(unit);
                shh[ut] = hv;
                usync(unit);
                if (ut < OUTD) {
                    const float* W2t = WT(16);
                    float a2 = 0.f;
#pragma unroll 8
                    for (int k = 0; k < HID; k++) a2 += shh[k] * W2t[k * OUTD + ut];
                    pair[side * OUTD + ut] = a2 + o2b[ut];
                }
                usync(unit);
            }
            {
                const float* Wt = WT(17);
                float acc = 0.f;
#pragma unroll 8
                for (int k = 0; k < 2 * OUTD; k++) acc += pair[k] * Wt[k * HID + ut];
                zz[ut] = fmaxf(acc + l1b[ut], 0.f);
            }
            usync(unit);
            if (ut < OUTD) {
                const float* Wt = WT(18);
                float a = 0.f;
#pragma unroll 8
                for (int k = 0; k < HID; k++) a += zz[k] * Wt[k * OUTD + ut];
                z2[ut] = fmaxf(a + l2b[ut], 0.f);
            }
            usync(unit);
            if (ut == 0) {
                float a = 0.f;
                for (int k = 0; k < OUTD; k++) a += z2[k] * l3W[k];
                a += l3b[0];
                out[p] = 1.f / (1.f + expf(-a));
            }
            usync(unit);
        }
    } else {
        // cleanup: restore zero-init sentinel state for the next replay
        for (int idx = (bid - 64) * NTHREADS + tid; idx < MCAP; idx += (NB - 64) * NTHREADS) {
            int u = idx >> 6, i = idx & 63;
            if (i < g_deg[u]) g_node2slot[g_srtNbr[u * DEGCAP + i]] = 0;
            if (i == 0) {
                g_node2slot[tp[u]] = 0;
                g_owner[tp[u]] = 0;
                g_degRaw[u] = 0;
            }
        }
        if (bid == 64 && tid == 0) { g_activeCount = 0; g_totalEntries = 0; }
    }
}

// ---------------- launch ----------------
extern "C" void kernel_launch(void* const* d_in, const int* in_sizes, int n_in,
                              void* d_out, int out_size) {
    const float* nf    = (const float*)d_in[0];
    const int*   ei    = (const int*)d_in[1];
    const float* ets   = (const float*)d_in[2];
    const int*   tp    = (const int*)d_in[3];
    const float* in_W  = (const float*)d_in[4];
    const float* in_b  = (const float*)d_in[5];
    const float* te_W1 = (const float*)d_in[6];
    const float* te_b1 = (const float*)d_in[7];
    const float* te_W2 = (const float*)d_in[8];
    const float* te_b2 = (const float*)d_in[9];
    const float* aiW   = (const float*)d_in[10];
    const float* aib   = (const float*)d_in[11];
    const float* aoW   = (const float*)d_in[12];
    const float* aob   = (const float*)d_in[13];
    const float* ftW   = (const float*)d_in[14];
    const float* ftb   = (const float*)d_in[15];
    const float* opW   = (const float*)d_in[16];
    const float* opb   = (const float*)d_in[17];
    const float* o1W   = (const float*)d_in[18];
    const float* o1b   = (const float*)d_in[19];
    const float* o2W   = (const float*)d_in[20];
    const float* o2b   = (const float*)d_in[21];
    const float* l1W   = (const float*)d_in[22];
    const float* l1b   = (const float*)d_in[23];
    const float* l2W   = (const float*)d_in[24];
    const float* l2b   = (const float*)d_in[25];
    const float* l3W   = (const float*)d_in[26];
    const float* l3b   = (const float*)d_in[27];
    float* out = (float*)d_out;

    k_main<<<NB, NTHREADS>>>(nf, ei, ets, tp, in_W, in_b, te_W1, te_b1, te_W2, te_b2,
                             aiW, aib, aoW, aob, ftW, ftb, opW, opb,
                             o1W, o1b, o2W, o2b, l1W, l1b, l2W, l2b, l3W, l3b, out);
}